// round 13
// baseline (speedup 1.0000x reference)
#include <cuda_runtime.h>

// Problem constants (fixed by the dataset)
#define NND   65536
#define EED   524288
#define BBD   256
#define EMBD  128
#define FEATD 64

// ---------------- scratch (static __device__ globals; zero-initialized) ----------------
__device__ float g_cur[NND * EMBD];
__device__ float g_new[NND * EMBD];
__device__ float g_agg0[NND * FEATD];
__device__ int   g_off[NND + 1];
__device__ int   g_cnt[NND];      // hist counts   (zeroed by k_agg0 for next call)
__device__ int   g_cnt2[NND];     // scatter cursor(zeroed by k_agg0 for next call)
__device__ int   g_srcs[EED];
__device__ float g_sm[4 * NND];
__device__ unsigned char g_keep[4 * NND];
__device__ int   g_klist[4 * NND];   // per (head, graph): local node indices
__device__ int   g_gkcnt[4 * BBD];   // kept count per (head, graph)
__device__ int   g_touch[NND];
__device__ float g_partS[512 * EMBD];
__device__ float g_partQ[512 * EMBD];
__device__ float g_mean[EMBD];
__device__ float g_gamrs[EMBD];
__device__ float g_logits[BBD * 4];
__device__ unsigned int g_done0;  // conv0 finalize counter (wraps to 0)
__device__ unsigned int g_done1;  // headstats finalize counter (wraps to 0)

__device__ __forceinline__ float lrelu(float v) { return v > 0.f ? v : 0.01f * v; }

// ---------------- CSR build ----------------
__global__ void k_hist(const int* __restrict__ dst) {
    int e = blockIdx.x * 256 + threadIdx.x;
    atomicAdd(&g_cnt[dst[e]], 1);
}

__global__ void __launch_bounds__(1024) k_scan() {
    __shared__ int wsum[32];
    int t = threadIdx.x, lane = t & 31, w = t >> 5;
    int base = t * 64;
    int s = 0;
#pragma unroll
    for (int i = 0; i < 16; i++) {
        int4 v = *reinterpret_cast<const int4*>(g_cnt + base + i * 4);
        s += v.x + v.y + v.z + v.w;
    }
    int inc = s;
    for (int o = 1; o < 32; o <<= 1) {
        int n = __shfl_up_sync(0xffffffffu, inc, o);
        if (lane >= o) inc += n;
    }
    if (lane == 31) wsum[w] = inc;
    __syncthreads();
    if (w == 0) {
        int v = wsum[lane];
        for (int o = 1; o < 32; o <<= 1) {
            int n = __shfl_up_sync(0xffffffffu, v, o);
            if (lane >= o) v += n;
        }
        wsum[lane] = v;
    }
    __syncthreads();
    int run = ((w > 0) ? wsum[w - 1] : 0) + (inc - s);
#pragma unroll
    for (int i = 0; i < 16; i++) {
        int4 v = *reinterpret_cast<const int4*>(g_cnt + base + i * 4);
        g_off[base + i * 4 + 0] = run; run += v.x;
        g_off[base + i * 4 + 1] = run; run += v.y;
        g_off[base + i * 4 + 2] = run; run += v.z;
        g_off[base + i * 4 + 3] = run; run += v.w;
    }
    if (t == 1023) g_off[NND] = EED;
}

__global__ void k_scatter(const int* __restrict__ src, const int* __restrict__ dst) {
    int e = blockIdx.x * 256 + threadIdx.x;
    int d = dst[e];
    int p = atomicAdd(&g_cnt2[d], 1);
    g_srcs[g_off[d] + p] = src[e];
}

// ---------------- conv0 max aggregation (warp/node, 4-edge unrolled) + cnt reset ----------------
__global__ void k_agg0(const float* __restrict__ x) {
    int gtid = blockIdx.x * blockDim.x + threadIdx.x;
    if (gtid < NND) { g_cnt[gtid] = 0; g_cnt2[gtid] = 0; }
    int warp = gtid >> 5;
    int lane = threadIdx.x & 31;
    if (warp >= NND) return;
    int o = g_off[warp], e = g_off[warp + 1];
    float2 m = make_float2(-3.402823466e38f, -3.402823466e38f);
    int j = o;
    for (; j + 3 < e; j += 4) {
        int s0 = g_srcs[j], s1 = g_srcs[j + 1], s2 = g_srcs[j + 2], s3 = g_srcs[j + 3];
        float2 v0 = *reinterpret_cast<const float2*>(x + s0 * FEATD + lane * 2);
        float2 v1 = *reinterpret_cast<const float2*>(x + s1 * FEATD + lane * 2);
        float2 v2 = *reinterpret_cast<const float2*>(x + s2 * FEATD + lane * 2);
        float2 v3 = *reinterpret_cast<const float2*>(x + s3 * FEATD + lane * 2);
        m.x = fmaxf(m.x, fmaxf(fmaxf(v0.x, v1.x), fmaxf(v2.x, v3.x)));
        m.y = fmaxf(m.y, fmaxf(fmaxf(v0.y, v1.y), fmaxf(v2.y, v3.y)));
    }
    for (; j < e; j++) {
        int s = g_srcs[j];
        float2 v = *reinterpret_cast<const float2*>(x + s * FEATD + lane * 2);
        m.x = fmaxf(m.x, v.x); m.y = fmaxf(m.y, v.y);
    }
    if (e == o) { m.x = 0.f; m.y = 0.f; }
    *reinterpret_cast<float2*>(g_agg0 + warp * FEATD + lane * 2) = m;
}

// ---------------- conv0 GEMM (scalar 8x8 tile) + fused stats + finalize ----------------
#define LDP 132
__global__ void __launch_bounds__(256) k_conv0(const float* __restrict__ x,
                                               const float* __restrict__ Wrel,
                                               const float* __restrict__ Wroot,
                                               const float* __restrict__ bias,
                                               const float* __restrict__ gamma) {
    extern __shared__ float sh[];
    float* sA = sh;              // [128 k][LDP] nodes contiguous
    float* sW = sh + 128 * LDP;  // [128 k][LDP] feats contiguous
    int t = threadIdx.x;
    int nbase = blockIdx.x * 128;
    for (int idx = t; idx < 8192; idx += 256) {
        int f = idx >> 6, k = idx & 63;
        sW[k * LDP + f]        = Wrel[idx];
        sW[(k + 64) * LDP + f] = Wroot[idx];
    }
    for (int idx = t; idx < 8192; idx += 256) {
        int node = idx >> 6, k = idx & 63;
        sA[k * LDP + node]        = g_agg0[nbase * 64 + idx];
        sA[(k + 64) * LDP + node] = x[nbase * 64 + idx];
    }
    __syncthreads();
    int tx = t & 15, ty = t >> 4;
    int f0 = tx * 8, n0 = ty * 8;
    float acc[8][8];
#pragma unroll
    for (int i = 0; i < 8; i++)
#pragma unroll
        for (int j = 0; j < 8; j++) acc[i][j] = 0.f;
#pragma unroll 2
    for (int k = 0; k < 128; k++) {
        float4 a0 = *reinterpret_cast<float4*>(sA + k * LDP + n0);
        float4 a1 = *reinterpret_cast<float4*>(sA + k * LDP + n0 + 4);
        float4 w0 = *reinterpret_cast<float4*>(sW + k * LDP + f0);
        float4 w1 = *reinterpret_cast<float4*>(sW + k * LDP + f0 + 4);
        float av[8] = {a0.x, a0.y, a0.z, a0.w, a1.x, a1.y, a1.z, a1.w};
        float wv[8] = {w0.x, w0.y, w0.z, w0.w, w1.x, w1.y, w1.z, w1.w};
#pragma unroll
        for (int i = 0; i < 8; i++)
#pragma unroll
            for (int j = 0; j < 8; j++) acc[i][j] += av[i] * wv[j];
    }
    float bb[8], s[8], q[8];
#pragma unroll
    for (int j = 0; j < 8; j++) { bb[j] = bias[f0 + j]; s[j] = 0.f; q[j] = 0.f; }
#pragma unroll
    for (int i = 0; i < 8; i++) {
        float v[8];
#pragma unroll
        for (int j = 0; j < 8; j++) {
            v[j] = lrelu(acc[i][j] + bb[j]);
            s[j] += v[j]; q[j] += v[j] * v[j];
        }
        float4* outp = reinterpret_cast<float4*>(g_new + (size_t)(nbase + n0 + i) * 128 + f0);
        outp[0] = make_float4(v[0], v[1], v[2], v[3]);
        outp[1] = make_float4(v[4], v[5], v[6], v[7]);
    }
    __syncthreads();
    float* sS = sA;
    float* sQ = sA + 2048;
#pragma unroll
    for (int j = 0; j < 8; j++) { sS[ty * 128 + f0 + j] = s[j]; sQ[ty * 128 + f0 + j] = q[j]; }
    __syncthreads();
    if (t < 128) {
        float ss = 0.f, qq = 0.f;
        for (int r = 0; r < 16; r++) { ss += sS[r * 128 + t]; qq += sQ[r * 128 + t]; }
        g_partS[blockIdx.x * 128 + t] = ss;
        g_partQ[blockIdx.x * 128 + t] = qq;
    }
    __shared__ bool islast;
    __shared__ float rs[256], rq[256];
    __threadfence();
    if (t == 0) {
        unsigned old = atomicInc(&g_done0, gridDim.x - 1);
        islast = (old == gridDim.x - 1);
    }
    __syncthreads();
    if (islast) {
        int col = t & 127, sl = t >> 7;
        float ss = 0.f, qq = 0.f;
#pragma unroll 8
        for (int ch = sl * 256; ch < sl * 256 + 256; ch++) {
            ss += g_partS[ch * 128 + col]; qq += g_partQ[ch * 128 + col];
        }
        rs[t] = ss; rq[t] = qq;
        __syncthreads();
        if (t < 128) {
            float S = rs[t] + rs[t + 128];
            float Q = rq[t] + rq[t + 128];
            float mean = S / (float)NND;
            float var  = Q / (float)NND - mean * mean;
            g_mean[t]  = mean;
            g_gamrs[t] = gamma[t] * rsqrtf(var + 1e-5f);
        }
    }
}

// ======== shared per-graph softmax helper (inlined pattern) is written inline below ========

// ---------------- fused BN-apply + scores + per-graph softmax + compaction ----------------
// grid 256 (one block per graph) x 256
__global__ void __launch_bounds__(256) k_bnsm(const float* __restrict__ beta,
                                              const float* __restrict__ w4,
                                              float minscore) {
    __shared__ float sw[512], s_m[128], s_g[128], s_b[128];
    __shared__ float s_sc[4 * 256];
    __shared__ float red[256];
    __shared__ int slist[256], wb[8], s_nk;
    int g = blockIdx.x, t = threadIdx.x;
    int w = t >> 5, lane = t & 31;
    for (int i = t; i < 512; i += 256) sw[i] = w4[i];
    if (t < 128) { s_m[t] = g_mean[t]; s_g[t] = g_gamrs[t]; s_b[t] = beta[t]; }
    __syncthreads();
    // phase 1: warp per node, 32 iterations
    int f = lane * 4;
    for (int it = 0; it < 32; it++) {
        int nl = it * 8 + w;
        int node = g * 256 + nl;
        float4 v = *reinterpret_cast<const float4*>(g_new + (size_t)node * 128 + f);
        float4 c;
        c.x = (v.x - s_m[f])     * s_g[f]     + s_b[f];
        c.y = (v.y - s_m[f + 1]) * s_g[f + 1] + s_b[f + 1];
        c.z = (v.z - s_m[f + 2]) * s_g[f + 2] + s_b[f + 2];
        c.w = (v.w - s_m[f + 3]) * s_g[f + 3] + s_b[f + 3];
        *reinterpret_cast<float4*>(g_cur + (size_t)node * 128 + f) = c;
#pragma unroll
        for (int h = 0; h < 4; h++) {
            const float* ww = sw + h * 128 + f;
            float p = c.x * ww[0] + c.y * ww[1] + c.z * ww[2] + c.w * ww[3];
            for (int o = 16; o > 0; o >>= 1) p += __shfl_xor_sync(0xffffffffu, p, o);
            if (lane == 0) s_sc[h * 256 + nl] = p;
        }
    }
    __syncthreads();
    // phase 2: per-head softmax + keep + ordered compaction + zero/touch
    int i = g * 256 + t;
    for (int h = 0; h < 4; h++) {
        float s = s_sc[h * 256 + t];
        red[t] = s; __syncthreads();
        for (int st = 128; st > 0; st >>= 1) { if (t < st) red[t] = fmaxf(red[t], red[t + st]); __syncthreads(); }
        float m = red[0]; __syncthreads();
        float e = expf(s - m);
        red[t] = e; __syncthreads();
        for (int st = 128; st > 0; st >>= 1) { if (t < st) red[t] += red[t + st]; __syncthreads(); }
        float S = red[0]; __syncthreads();
        float sm = e / (S + 1e-16f);
        red[t] = sm; __syncthreads();
        for (int st = 128; st > 0; st >>= 1) { if (t < st) red[t] = fmaxf(red[t], red[t + st]); __syncthreads(); }
        float smax = red[0];
        float thr = fminf(smax - 1e-7f, minscore);
        bool keep = sm > thr;
        g_sm[h * NND + i] = sm;
        g_keep[h * NND + i] = keep ? 1 : 0;
        unsigned int bm = __ballot_sync(0xffffffffu, keep);
        if (lane == 0) wb[w] = __popc(bm);
        __syncthreads();
        if (t == 0) {
            int a = 0;
            for (int k = 0; k < 8; k++) { int v = wb[k]; wb[k] = a; a += v; }
            s_nk = a;
        }
        __syncthreads();
        if (keep) slist[wb[w] + __popc(bm & ((1u << lane) - 1u))] = t;
        __syncthreads();
        int nk = s_nk;
        if (t == 0) g_gkcnt[h * 256 + g] = nk;
        for (int li = 0; li < nk; li++) {
            int nl = slist[li];
            if (t < 128) g_new[(size_t)(g * 256 + nl) * 128 + t] = 0.f;
            if (t == 0) { g_klist[h * NND + g * 256 + li] = nl; g_touch[g * 256 + nl] = 1; }
        }
        __syncthreads();
    }
}

// ---------------- fused residual + scores + per-graph softmax + compaction ----------------
__global__ void __launch_bounds__(256) k_ressm(const float* __restrict__ beta,
                                               const float* __restrict__ w4,
                                               float minscore) {
    __shared__ float sw[512], s_m[128], s_g[128], s_b[128];
    __shared__ float s_sc[4 * 256];
    __shared__ float red[256];
    __shared__ int slist[256], wb[8], s_nk;
    int g = blockIdx.x, t = threadIdx.x;
    int w = t >> 5, lane = t & 31;
    for (int i = t; i < 512; i += 256) sw[i] = w4[i];
    if (t < 128) { s_m[t] = g_mean[t]; s_g[t] = g_gamrs[t]; s_b[t] = beta[t]; }
    __syncthreads();
    int f = lane * 4;
    for (int it = 0; it < 32; it++) {
        int nl = it * 8 + w;
        int node = g * 256 + nl;
        int tch = g_touch[node];
        float4 v = make_float4(0.f, 0.f, 0.f, 0.f);
        if (tch) v = *reinterpret_cast<const float4*>(g_new + (size_t)node * 128 + f);
        float4 cu = *reinterpret_cast<const float4*>(g_cur + (size_t)node * 128 + f);
        float4 c;
        c.x = 0.5f * cu.x + 0.25f * ((v.x - s_m[f])     * s_g[f]     + s_b[f]);
        c.y = 0.5f * cu.y + 0.25f * ((v.y - s_m[f + 1]) * s_g[f + 1] + s_b[f + 1]);
        c.z = 0.5f * cu.z + 0.25f * ((v.z - s_m[f + 2]) * s_g[f + 2] + s_b[f + 2]);
        c.w = 0.5f * cu.w + 0.25f * ((v.w - s_m[f + 3]) * s_g[f + 3] + s_b[f + 3]);
        *reinterpret_cast<float4*>(g_cur + (size_t)node * 128 + f) = c;
        if (lane == 0) g_touch[node] = 0;
#pragma unroll
        for (int h = 0; h < 4; h++) {
            const float* ww = sw + h * 128 + f;
            float p = c.x * ww[0] + c.y * ww[1] + c.z * ww[2] + c.w * ww[3];
            for (int o = 16; o > 0; o >>= 1) p += __shfl_xor_sync(0xffffffffu, p, o);
            if (lane == 0) s_sc[h * 256 + nl] = p;
        }
    }
    __syncthreads();
    int i = g * 256 + t;
    for (int h = 0; h < 4; h++) {
        float s = s_sc[h * 256 + t];
        red[t] = s; __syncthreads();
        for (int st = 128; st > 0; st >>= 1) { if (t < st) red[t] = fmaxf(red[t], red[t + st]); __syncthreads(); }
        float m = red[0]; __syncthreads();
        float e = expf(s - m);
        red[t] = e; __syncthreads();
        for (int st = 128; st > 0; st >>= 1) { if (t < st) red[t] += red[t + st]; __syncthreads(); }
        float S = red[0]; __syncthreads();
        float sm = e / (S + 1e-16f);
        red[t] = sm; __syncthreads();
        for (int st = 128; st > 0; st >>= 1) { if (t < st) red[t] = fmaxf(red[t], red[t + st]); __syncthreads(); }
        float smax = red[0];
        float thr = fminf(smax - 1e-7f, minscore);
        bool keep = sm > thr;
        g_sm[h * NND + i] = sm;
        g_keep[h * NND + i] = keep ? 1 : 0;
        unsigned int bm = __ballot_sync(0xffffffffu, keep);
        if (lane == 0) wb[w] = __popc(bm);
        __syncthreads();
        if (t == 0) {
            int a = 0;
            for (int k = 0; k < 8; k++) { int v = wb[k]; wb[k] = a; a += v; }
            s_nk = a;
        }
        __syncthreads();
        if (keep) slist[wb[w] + __popc(bm & ((1u << lane) - 1u))] = t;
        __syncthreads();
        int nk = s_nk;
        if (t == 0) g_gkcnt[h * 256 + g] = nk;
        for (int li = 0; li < nk; li++) {
            int nl = slist[li];
            if (t < 128) g_new[(size_t)(g * 256 + nl) * 128 + t] = 0.f;
            if (t == 0) { g_klist[h * NND + g * 256 + li] = nl; g_touch[g * 256 + nl] = 1; }
        }
        __syncthreads();
    }
}

// ---------------- head conv on kept nodes + stats + finalize (grid (256,4)) ----------------
__global__ void __launch_bounds__(256) k_headstats(const float* __restrict__ Wrel,
                                                   const float* __restrict__ Wroot,
                                                   const float* __restrict__ bias,
                                                   const float* __restrict__ gamma) {
    __shared__ float s_agg[8][128];
    __shared__ float s_xp[8][128];
    __shared__ float sS[8][32], sQ[8][32];
    int g = blockIdx.x, h = blockIdx.y;
    int kc = g_gkcnt[h * 256 + g];
    int w = threadIdx.x >> 5, lane = threadIdx.x & 31;
    const float* smh = g_sm + h * NND;
    const unsigned char* kph = g_keep + h * NND;
    float s = 0.f, q = 0.f;
    for (int entry = w; entry < kc; entry += 8) {
        int i = g * 256 + g_klist[h * NND + g * 256 + entry];
        int o = g_off[i];
        int c = g_off[i + 1] - o;
        float a0 = -3.402823466e38f, a1 = a0, a2 = a0, a3 = a0;
        bool any = false;
        for (int j = 0; j < c; j++) {
            int sr = g_srcs[o + j];
            if (kph[sr]) {
                any = true;
                float ss = smh[sr];
                const float* cr = g_cur + (size_t)sr * 128;
                a0 = fmaxf(a0, cr[lane]      * ss);
                a1 = fmaxf(a1, cr[lane + 32] * ss);
                a2 = fmaxf(a2, cr[lane + 64] * ss);
                a3 = fmaxf(a3, cr[lane + 96] * ss);
            }
        }
        if (!any) { a0 = a1 = a2 = a3 = 0.f; }
        float smi = smh[i];
        const float* ci = g_cur + (size_t)i * 128;
        s_agg[w][lane] = a0; s_agg[w][lane + 32] = a1; s_agg[w][lane + 64] = a2; s_agg[w][lane + 96] = a3;
        s_xp[w][lane]      = ci[lane]      * smi;
        s_xp[w][lane + 32] = ci[lane + 32] * smi;
        s_xp[w][lane + 64] = ci[lane + 64] * smi;
        s_xp[w][lane + 96] = ci[lane + 96] * smi;
        __syncwarp();
        const float* wr = Wrel  + (h * 32 + lane) * 128;
        const float* wo = Wroot + (h * 32 + lane) * 128;
        float acc = bias[h * 32 + lane];
#pragma unroll 4
        for (int k = 0; k < 128; k++) acc += s_agg[w][k] * wr[k] + s_xp[w][k] * wo[k];
        float v = lrelu(acc);
        g_new[(size_t)i * 128 + h * 32 + lane] = v;
        s += v; q += v * v;
        __syncwarp();
    }
    sS[w][lane] = s; sQ[w][lane] = q;
    __syncthreads();
    if (w == 0) {
        float ss = 0.f, qq = 0.f;
#pragma unroll
        for (int r = 0; r < 8; r++) { ss += sS[r][lane]; qq += sQ[r][lane]; }
        g_partS[(h * 256 + g) * 32 + lane] = ss;
        g_partQ[(h * 256 + g) * 32 + lane] = qq;
    }
    // last-block finalize (1024 blocks)
    __shared__ bool islast;
    __shared__ float rs[256], rq[256];
    __threadfence();
    if (threadIdx.x == 0) {
        unsigned old = atomicInc(&g_done1, 1023);
        islast = (old == 1023);
    }
    __syncthreads();
    if (islast) {
        int t = threadIdx.x;
        int c = t & 127, sl = t >> 7;
        int hh = c >> 5, cc = c & 31;
        float ss = 0.f, qq = 0.f;
#pragma unroll 8
        for (int gg = sl * 128; gg < sl * 128 + 128; gg++) {
            ss += g_partS[(hh * 256 + gg) * 32 + cc];
            qq += g_partQ[(hh * 256 + gg) * 32 + cc];
        }
        rs[t] = ss; rq[t] = qq;
        __syncthreads();
        if (t < 128) {
            float S = rs[t] + rs[t + 128];
            float Q = rq[t] + rq[t + 128];
            float mean = S / (float)NND;
            float var  = Q / (float)NND - mean * mean;
            g_mean[t]  = mean;
            g_gamrs[t] = gamma[t] * rsqrtf(var + 1e-5f);
        }
    }
}

// ---------------- final fused: residual + cls scores + softmax + gate + attn + MLP ----------------
// grid 256 (one block per graph) x 256
__global__ void __launch_bounds__(256) k_ressm_cls(const float* __restrict__ beta,
                                                   const float* __restrict__ w4,
                                                   const float* __restrict__ gW1, const float* __restrict__ gb1,
                                                   const float* __restrict__ gW2, const float* __restrict__ gb2,
                                                   const float* __restrict__ fW1, const float* __restrict__ fb1,
                                                   const float* __restrict__ fW2, const float* __restrict__ fb2) {
    __shared__ float sw[512], s_m[128], s_g[128], s_b[128];
    __shared__ float s_sc[4 * 256];
    __shared__ float red[256], s_sm[256], s_xp[128], s_term[128], s_gate[256];
    __shared__ int slist[256], wb[8], s_nk;
    int g = blockIdx.x, t = threadIdx.x;
    int w = t >> 5, lane = t & 31;
    for (int i = t; i < 512; i += 256) sw[i] = w4[i];
    if (t < 128) { s_m[t] = g_mean[t]; s_g[t] = g_gamrs[t]; s_b[t] = beta[t]; }
    __syncthreads();
    // phase 1: residual + 4 classifier score dots
    int f4 = lane * 4;
    for (int it = 0; it < 32; it++) {
        int nl = it * 8 + w;
        int node = g * 256 + nl;
        int tch = g_touch[node];
        float4 v = make_float4(0.f, 0.f, 0.f, 0.f);
        if (tch) v = *reinterpret_cast<const float4*>(g_new + (size_t)node * 128 + f4);
        float4 cu = *reinterpret_cast<const float4*>(g_cur + (size_t)node * 128 + f4);
        float4 c;
        c.x = 0.5f * cu.x + 0.25f * ((v.x - s_m[f4])     * s_g[f4]     + s_b[f4]);
        c.y = 0.5f * cu.y + 0.25f * ((v.y - s_m[f4 + 1]) * s_g[f4 + 1] + s_b[f4 + 1]);
        c.z = 0.5f * cu.z + 0.25f * ((v.z - s_m[f4 + 2]) * s_g[f4 + 2] + s_b[f4 + 2]);
        c.w = 0.5f * cu.w + 0.25f * ((v.w - s_m[f4 + 3]) * s_g[f4 + 3] + s_b[f4 + 3]);
        *reinterpret_cast<float4*>(g_cur + (size_t)node * 128 + f4) = c;
        if (lane == 0) g_touch[node] = 0;   // clean state for next call
#pragma unroll
        for (int h = 0; h < 4; h++) {
            const float* ww = sw + h * 128 + f4;
            float p = c.x * ww[0] + c.y * ww[1] + c.z * ww[2] + c.w * ww[3];
            for (int o = 16; o > 0; o >>= 1) p += __shfl_xor_sync(0xffffffffu, p, o);
            if (lane == 0) s_sc[h * 256 + nl] = p;
        }
    }
    __syncthreads();
    // phase 2: per classifier head: softmax(0.8) -> keep -> gate -> attention -> MLP -> logit
    int f = t >> 1, hf = t & 1;
    for (int c = 0; c < 4; c++) {
        float s = s_sc[c * 256 + t];
        red[t] = s; __syncthreads();
        for (int st = 128; st > 0; st >>= 1) { if (t < st) red[t] = fmaxf(red[t], red[t + st]); __syncthreads(); }
        float m = red[0]; __syncthreads();
        float e = expf(s - m);
        red[t] = e; __syncthreads();
        for (int st = 128; st > 0; st >>= 1) { if (t < st) red[t] += red[t + st]; __syncthreads(); }
        float S0 = red[0]; __syncthreads();
        float sm = e / (S0 + 1e-16f);
        red[t] = sm; __syncthreads();
        for (int st = 128; st > 0; st >>= 1) { if (t < st) red[t] = fmaxf(red[t], red[t + st]); __syncthreads(); }
        float smax = red[0];
        float thr = fminf(smax - 1e-7f, 0.8f);
        bool keep = sm > thr;
        s_sm[t] = sm;
        unsigned int bm = __ballot_sync(0xffffffffu, keep);
        if (lane == 0) wb[w] = __popc(bm);
        __syncthreads();
        if (t == 0) {
            int a = 0;
            for (int k = 0; k < 8; k++) { int v = wb[k]; wb[k] = a; a += v; }
            s_nk = a;
        }
        __syncthreads();
        if (keep) slist[wb[w] + __popc(bm & ((1u << lane) - 1u))] = t;
        __syncthreads();
        int nk = s_nk;
        // gate MLP per kept node
        for (int li = 0; li < nk; li++) {
            int tk = slist[li];
            float smk = s_sm[tk];
            if (t < 128) s_xp[t] = g_cur[(size_t)(g * 256 + tk) * 128 + t] * smk;
            __syncthreads();
            const float* w1 = gW1 + ((size_t)c * 128 + f) * 128 + hf * 64;
            float acc = 0.f;
#pragma unroll 8
            for (int k = 0; k < 64; k++) acc += s_xp[hf * 64 + k] * w1[k];
            red[t] = acc; __syncthreads();
            if (t < 128) {
                float comb = red[2 * t] + red[2 * t + 1] + gb1[c * 128 + t];
                s_term[t] = lrelu(comb) * gW2[c * 128 + t];
            }
            __syncthreads();
            for (int st = 64; st > 0; st >>= 1) { if (t < st) s_term[t] += s_term[t + st]; __syncthreads(); }
            if (t == 0) s_gate[li] = s_term[0] + gb2[c];
            __syncthreads();
        }
        // attention softmax over kept (thread 0, fixed order)
        if (t == 0) {
            float M = -3.402823466e38f;
            for (int li = 0; li < nk; li++) M = fmaxf(M, s_gate[li]);
            float S = 0.f;
            for (int li = 0; li < nk; li++) S += expf(s_gate[li] - M);
            float inv = 1.f / (S + 1e-16f);
            for (int li = 0; li < nk; li++)
                s_gate[li] = expf(s_gate[li] - M) * inv * s_sm[slist[li]];
        }
        __syncthreads();
        if (t < 128) {
            float pf = 0.f;
            for (int li = 0; li < nk; li++)
                pf += s_gate[li] * g_cur[(size_t)(g * 256 + slist[li]) * 128 + t];
            s_xp[t] = pf;
        }
        __syncthreads();
        const float* w1 = fW1 + ((size_t)c * 128 + f) * 128 + hf * 64;
        float acc = 0.f;
#pragma unroll 8
        for (int k = 0; k < 64; k++) acc += s_xp[hf * 64 + k] * w1[k];
        red[t] = acc; __syncthreads();
        if (t < 128) {
            float comb = red[2 * t] + red[2 * t + 1] + fb1[c * 128 + t];
            s_term[t] = lrelu(comb) * fW2[c * 128 + t];
        }
        __syncthreads();
        for (int st = 64; st > 0; st >>= 1) { if (t < st) s_term[t] += s_term[t + st]; __syncthreads(); }
        if (t == 0) g_logits[g * 4 + c] = s_term[0] + fb2[c];
        __syncthreads();
    }
}

__global__ void k_logsm(float* __restrict__ out) {  // 1 x 256
    int g = threadIdx.x;
    float l0 = g_logits[g * 4 + 0], l1 = g_logits[g * 4 + 1];
    float l2 = g_logits[g * 4 + 2], l3 = g_logits[g * 4 + 3];
    float m = fmaxf(fmaxf(l0, l1), fmaxf(l2, l3));
    float s = expf(l0 - m) + expf(l1 - m) + expf(l2 - m) + expf(l3 - m);
    float ls = m + logf(s);
    out[g * 4 + 0] = l0 - ls;
    out[g * 4 + 1] = l1 - ls;
    out[g * 4 + 2] = l2 - ls;
    out[g * 4 + 3] = l3 - ls;
}

// ---------------------------------- launcher ----------------------------------
extern "C" void kernel_launch(void* const* d_in, const int* in_sizes, int n_in,
                              void* d_out, int out_size) {
    const float* x      = (const float*)d_in[0];
    const int*   ei     = (const int*)  d_in[1];
    const int*   src    = ei;
    const int*   dst    = ei + EED;
    const float* Wrel0  = (const float*)d_in[3];
    const float* Wroot0 = (const float*)d_in[4];
    const float* b0     = (const float*)d_in[5];
    const float* bn0g   = (const float*)d_in[6];
    const float* bn0b   = (const float*)d_in[7];
    const float* bpw    = (const float*)d_in[8];
    const float* bWrel  = (const float*)d_in[9];
    const float* bWroot = (const float*)d_in[10];
    const float* bbias  = (const float*)d_in[11];
    const float* bbng   = (const float*)d_in[12];
    const float* bbnb   = (const float*)d_in[13];
    const float* cpw    = (const float*)d_in[14];
    const float* gW1    = (const float*)d_in[15];
    const float* gb1    = (const float*)d_in[16];
    const float* gW2    = (const float*)d_in[17];
    const float* gb2    = (const float*)d_in[18];
    const float* fW1    = (const float*)d_in[19];
    const float* fb1    = (const float*)d_in[20];
    const float* fW2    = (const float*)d_in[21];
    const float* fb2    = (const float*)d_in[22];
    float* out = (float*)d_out;

    // CSR build
    k_hist<<<EED / 256, 256>>>(dst);
    k_scan<<<1, 1024>>>();
    k_scatter<<<EED / 256, 256>>>(src, dst);

    // conv0 (+stats finalize inside)
    k_agg0<<<NND / 8, 256>>>(x);
    static int smem_set = 0;
    if (!smem_set) {
        cudaFuncSetAttribute(k_conv0, cudaFuncAttributeMaxDynamicSharedMemorySize,
                             2 * 128 * LDP * 4);
        smem_set = 1;
    }
    k_conv0<<<NND / 128, 256, 2 * 128 * LDP * 4>>>(x, Wrel0, Wroot0, b0, bn0g);

    // block 0
    k_bnsm<<<BBD, 256>>>(bn0b, bpw, 0.7f);
    k_headstats<<<dim3(BBD, 4), 256>>>(bWrel, bWroot, bbias, bbng);
    // block 1 (residual with block0 bn, scores for block1 pools)
    k_ressm<<<BBD, 256>>>(bbnb, bpw + 4 * 128, 0.7f);
    k_headstats<<<dim3(BBD, 4), 256>>>(bWrel + 4 * 32 * 128, bWroot + 4 * 32 * 128,
                                       bbias + 4 * 32, bbng + 128);
    // final residual + classifier (all fused) + log_softmax
    k_ressm_cls<<<BBD, 256>>>(bbnb + 128, cpw, gW1, gb1, gW2, gb2, fW1, fb1, fW2, fb2);
    k_logsm<<<1, 256>>>(out);
}

// round 15
// speedup vs baseline: 1.0583x; 1.0583x over previous
#include <cuda_runtime.h>

// Problem constants (fixed by the dataset)
#define NND   65536
#define EED   524288
#define BBD   256
#define EMBD  128
#define FEATD 64

// ---------------- scratch (static __device__ globals; zero-initialized) ----------------
__device__ float g_cur[NND * EMBD];
__device__ float g_new[NND * EMBD];
__device__ float g_agg0[NND * FEATD];
__device__ int   g_off[NND + 1];
__device__ int   g_cnt[NND];      // hist counts   (zeroed by k_agg0 for next call)
__device__ int   g_cnt2[NND];     // scatter cursor(zeroed by k_agg0 for next call)
__device__ int   g_srcs[EED];
__device__ float g_score[4 * NND];
__device__ float g_sm[4 * NND];
__device__ unsigned char g_keep[4 * NND];
__device__ int   g_klist[4 * NND];   // per (head, graph): local node indices, ordered
__device__ int   g_gkcnt[4 * BBD];   // kept count per (head, graph)
__device__ int   g_touch[NND];
__device__ float g_partS[512 * EMBD];
__device__ float g_partQ[512 * EMBD];
__device__ float g_mean[EMBD];
__device__ float g_gamrs[EMBD];
__device__ float g_logits[BBD * 4];
__device__ unsigned int g_done0;        // conv0 finalize counter (wraps to 0)
__device__ unsigned int g_done1;        // headstats finalize counter (wraps to 0)
__device__ unsigned int g_cdone[BBD];   // per-graph k_cls completion (wraps to 0)

__device__ __forceinline__ float lrelu(float v) { return v > 0.f ? v : 0.01f * v; }

// ---------------- CSR build ----------------
__global__ void k_hist(const int* __restrict__ dst) {
    int e = (blockIdx.x * 256 + threadIdx.x) * 2;
    int2 d = *reinterpret_cast<const int2*>(dst + e);
    atomicAdd(&g_cnt[d.x], 1);
    atomicAdd(&g_cnt[d.y], 1);
}

// single-block scan: 1024 threads, 64 contiguous counts each
__global__ void __launch_bounds__(1024) k_scan() {
    __shared__ int wsum[32];
    int t = threadIdx.x, lane = t & 31, w = t >> 5;
    int base = t * 64;
    int s = 0;
#pragma unroll
    for (int i = 0; i < 16; i++) {
        int4 v = *reinterpret_cast<const int4*>(g_cnt + base + i * 4);
        s += v.x + v.y + v.z + v.w;
    }
    int inc = s;
    for (int o = 1; o < 32; o <<= 1) {
        int n = __shfl_up_sync(0xffffffffu, inc, o);
        if (lane >= o) inc += n;
    }
    if (lane == 31) wsum[w] = inc;
    __syncthreads();
    if (w == 0) {
        int v = wsum[lane];
        for (int o = 1; o < 32; o <<= 1) {
            int n = __shfl_up_sync(0xffffffffu, v, o);
            if (lane >= o) v += n;
        }
        wsum[lane] = v;
    }
    __syncthreads();
    int run = ((w > 0) ? wsum[w - 1] : 0) + (inc - s);
#pragma unroll
    for (int i = 0; i < 16; i++) {
        int4 v = *reinterpret_cast<const int4*>(g_cnt + base + i * 4);
        g_off[base + i * 4 + 0] = run; run += v.x;
        g_off[base + i * 4 + 1] = run; run += v.y;
        g_off[base + i * 4 + 2] = run; run += v.z;
        g_off[base + i * 4 + 3] = run; run += v.w;
    }
    if (t == 1023) g_off[NND] = EED;
}

__global__ void k_scatter(const int* __restrict__ src, const int* __restrict__ dst) {
    int e = (blockIdx.x * 256 + threadIdx.x) * 2;
    int2 d = *reinterpret_cast<const int2*>(dst + e);
    int2 sc = *reinterpret_cast<const int2*>(src + e);
    int p0 = atomicAdd(&g_cnt2[d.x], 1);
    g_srcs[g_off[d.x] + p0] = sc.x;
    int p1 = atomicAdd(&g_cnt2[d.y], 1);
    g_srcs[g_off[d.y] + p1] = sc.y;
}

// ---------------- conv0 max aggregation: 2 nodes/warp, 16 lanes x float4 ----------------
__global__ void k_agg0(const float* __restrict__ x) {
    int gtid = blockIdx.x * blockDim.x + threadIdx.x;
    if (gtid < NND) { g_cnt[gtid] = 0; g_cnt2[gtid] = 0; }   // restore invariant for next call
    int warp = gtid >> 5;
    int lane = threadIdx.x & 31;
    int node = warp * 2 + (lane >> 4);
    int sub = lane & 15;
    if (node >= NND) return;
    int o = g_off[node], e = g_off[node + 1];
    float4 m = make_float4(-3.402823466e38f, -3.402823466e38f, -3.402823466e38f, -3.402823466e38f);
    int j = o;
    for (; j + 1 < e; j += 2) {
        int s0 = g_srcs[j], s1 = g_srcs[j + 1];
        float4 v0 = *reinterpret_cast<const float4*>(x + s0 * FEATD + sub * 4);
        float4 v1 = *reinterpret_cast<const float4*>(x + s1 * FEATD + sub * 4);
        m.x = fmaxf(m.x, fmaxf(v0.x, v1.x));
        m.y = fmaxf(m.y, fmaxf(v0.y, v1.y));
        m.z = fmaxf(m.z, fmaxf(v0.z, v1.z));
        m.w = fmaxf(m.w, fmaxf(v0.w, v1.w));
    }
    for (; j < e; j++) {
        int s = g_srcs[j];
        float4 v = *reinterpret_cast<const float4*>(x + s * FEATD + sub * 4);
        m.x = fmaxf(m.x, v.x); m.y = fmaxf(m.y, v.y);
        m.z = fmaxf(m.z, v.z); m.w = fmaxf(m.w, v.w);
    }
    if (e == o) m = make_float4(0.f, 0.f, 0.f, 0.f);
    *reinterpret_cast<float4*>(g_agg0 + node * FEATD + sub * 4) = m;
}

// ---------------- conv0 GEMM (scalar 8x8 tile) + fused stats + finalize ----------------
#define LDP 132
__global__ void __launch_bounds__(256) k_conv0(const float* __restrict__ x,
                                               const float* __restrict__ Wrel,
                                               const float* __restrict__ Wroot,
                                               const float* __restrict__ bias,
                                               const float* __restrict__ gamma) {
    extern __shared__ float sh[];
    float* sA = sh;              // [128 k][LDP] nodes contiguous
    float* sW = sh + 128 * LDP;  // [128 k][LDP] feats contiguous
    int t = threadIdx.x;
    int nbase = blockIdx.x * 128;
    for (int idx = t; idx < 8192; idx += 256) {
        int f = idx >> 6, k = idx & 63;
        sW[k * LDP + f]        = Wrel[idx];
        sW[(k + 64) * LDP + f] = Wroot[idx];
    }
    for (int idx = t; idx < 8192; idx += 256) {
        int node = idx >> 6, k = idx & 63;
        sA[k * LDP + node]        = g_agg0[nbase * 64 + idx];
        sA[(k + 64) * LDP + node] = x[nbase * 64 + idx];
    }
    __syncthreads();
    int tx = t & 15, ty = t >> 4;
    int f0 = tx * 8, n0 = ty * 8;
    float acc[8][8];
#pragma unroll
    for (int i = 0; i < 8; i++)
#pragma unroll
        for (int j = 0; j < 8; j++) acc[i][j] = 0.f;
#pragma unroll 2
    for (int k = 0; k < 128; k++) {
        float4 a0 = *reinterpret_cast<float4*>(sA + k * LDP + n0);
        float4 a1 = *reinterpret_cast<float4*>(sA + k * LDP + n0 + 4);
        float4 w0 = *reinterpret_cast<float4*>(sW + k * LDP + f0);
        float4 w1 = *reinterpret_cast<float4*>(sW + k * LDP + f0 + 4);
        float av[8] = {a0.x, a0.y, a0.z, a0.w, a1.x, a1.y, a1.z, a1.w};
        float wv[8] = {w0.x, w0.y, w0.z, w0.w, w1.x, w1.y, w1.z, w1.w};
#pragma unroll
        for (int i = 0; i < 8; i++)
#pragma unroll
            for (int j = 0; j < 8; j++) acc[i][j] += av[i] * wv[j];
    }
    float bb[8], s[8], q[8];
#pragma unroll
    for (int j = 0; j < 8; j++) { bb[j] = bias[f0 + j]; s[j] = 0.f; q[j] = 0.f; }
#pragma unroll
    for (int i = 0; i < 8; i++) {
        float v[8];
#pragma unroll
        for (int j = 0; j < 8; j++) {
            v[j] = lrelu(acc[i][j] + bb[j]);
            s[j] += v[j]; q[j] += v[j] * v[j];
        }
        float4* outp = reinterpret_cast<float4*>(g_new + (size_t)(nbase + n0 + i) * 128 + f0);
        outp[0] = make_float4(v[0], v[1], v[2], v[3]);
        outp[1] = make_float4(v[4], v[5], v[6], v[7]);
    }
    __syncthreads();
    float* sS = sA;
    float* sQ = sA + 2048;
#pragma unroll
    for (int j = 0; j < 8; j++) { sS[ty * 128 + f0 + j] = s[j]; sQ[ty * 128 + f0 + j] = q[j]; }
    __syncthreads();
    if (t < 128) {
        float ss = 0.f, qq = 0.f;
        for (int r = 0; r < 16; r++) { ss += sS[r * 128 + t]; qq += sQ[r * 128 + t]; }
        g_partS[blockIdx.x * 128 + t] = ss;
        g_partQ[blockIdx.x * 128 + t] = qq;
    }
    __shared__ bool islast;
    __shared__ float rs[256], rq[256];
    __threadfence();
    if (t == 0) {
        unsigned old = atomicInc(&g_done0, gridDim.x - 1);
        islast = (old == gridDim.x - 1);
    }
    __syncthreads();
    if (islast) {
        int col = t & 127, sl = t >> 7;
        float ss = 0.f, qq = 0.f;
#pragma unroll 8
        for (int ch = sl * 256; ch < sl * 256 + 256; ch++) {
            ss += g_partS[ch * 128 + col]; qq += g_partQ[ch * 128 + col];
        }
        rs[t] = ss; rq[t] = qq;
        __syncthreads();
        if (t < 128) {
            float S = rs[t] + rs[t + 128];
            float Q = rq[t] + rq[t + 128];
            float mean = S / (float)NND;
            float var  = Q / (float)NND - mean * mean;
            g_mean[t]  = mean;
            g_gamrs[t] = gamma[t] * rsqrtf(var + 1e-5f);
        }
    }
}

// ---------------- fused BN-apply + pooling scores (wide: 8192 blocks) ----------------
__global__ void __launch_bounds__(256) k_bn_scores(const float* __restrict__ beta,
                                                   const float* __restrict__ w4) {
    __shared__ float sw[512], s_m[128], s_g[128], s_b[128];
    int t = threadIdx.x;
    for (int i = t; i < 512; i += 256) sw[i] = w4[i];
    if (t < 128) { s_m[t] = g_mean[t]; s_g[t] = g_gamrs[t]; s_b[t] = beta[t]; }
    __syncthreads();
    int w = t >> 5, lane = t & 31;
    int node = blockIdx.x * 8 + w;
    int f = lane * 4;
    float4 v = *reinterpret_cast<const float4*>(g_new + (size_t)node * 128 + f);
    float4 c;
    c.x = (v.x - s_m[f])     * s_g[f]     + s_b[f];
    c.y = (v.y - s_m[f + 1]) * s_g[f + 1] + s_b[f + 1];
    c.z = (v.z - s_m[f + 2]) * s_g[f + 2] + s_b[f + 2];
    c.w = (v.w - s_m[f + 3]) * s_g[f + 3] + s_b[f + 3];
    *reinterpret_cast<float4*>(g_cur + (size_t)node * 128 + f) = c;
#pragma unroll
    for (int h = 0; h < 4; h++) {
        const float* ww = sw + h * 128 + f;
        float p = c.x * ww[0] + c.y * ww[1] + c.z * ww[2] + c.w * ww[3];
        for (int o = 16; o > 0; o >>= 1) p += __shfl_xor_sync(0xffffffffu, p, o);
        if (lane == 0) g_score[h * NND + node] = p;
    }
}

// ---------------- fused residual + pooling scores (wide; +touch clear) ----------------
__global__ void __launch_bounds__(256) k_res_scores(const float* __restrict__ beta,
                                                    const float* __restrict__ w4) {
    __shared__ float sw[512], s_m[128], s_g[128], s_b[128];
    int t = threadIdx.x;
    for (int i = t; i < 512; i += 256) sw[i] = w4[i];
    if (t < 128) { s_m[t] = g_mean[t]; s_g[t] = g_gamrs[t]; s_b[t] = beta[t]; }
    __syncthreads();
    int w = t >> 5, lane = t & 31;
    int node = blockIdx.x * 8 + w;
    int f = lane * 4;
    int tch = g_touch[node];
    float4 v = make_float4(0.f, 0.f, 0.f, 0.f);
    if (tch) v = *reinterpret_cast<const float4*>(g_new + (size_t)node * 128 + f);
    float4 cu = *reinterpret_cast<const float4*>(g_cur + (size_t)node * 128 + f);
    float4 c;
    c.x = 0.5f * cu.x + 0.25f * ((v.x - s_m[f])     * s_g[f]     + s_b[f]);
    c.y = 0.5f * cu.y + 0.25f * ((v.y - s_m[f + 1]) * s_g[f + 1] + s_b[f + 1]);
    c.z = 0.5f * cu.z + 0.25f * ((v.z - s_m[f + 2]) * s_g[f + 2] + s_b[f + 2]);
    c.w = 0.5f * cu.w + 0.25f * ((v.w - s_m[f + 3]) * s_g[f + 3] + s_b[f + 3]);
    *reinterpret_cast<float4*>(g_cur + (size_t)node * 128 + f) = c;
#pragma unroll
    for (int h = 0; h < 4; h++) {
        const float* ww = sw + h * 128 + f;
        float p = c.x * ww[0] + c.y * ww[1] + c.z * ww[2] + c.w * ww[3];
        for (int o = 16; o > 0; o >>= 1) p += __shfl_xor_sync(0xffffffffu, p, o);
        if (lane == 0) g_score[h * NND + node] = p;
    }
    __syncthreads();
    if (t < 8) g_touch[blockIdx.x * 8 + t] = 0;
}

// ---------------- per-graph softmax + keep + ORDERED compaction + kept-row zero/touch ----
__global__ void k_softmax(float minscore) {  // grid (B, 4) x 256
    __shared__ float red[256];
    __shared__ int slist[256], wb[8];
    __shared__ int s_nk;
    int g = blockIdx.x, h = blockIdx.y, t = threadIdx.x;
    int w = t >> 5, lane = t & 31;
    int i = g * 256 + t;
    float s = g_score[h * NND + i];
    red[t] = s; __syncthreads();
    for (int st = 128; st > 0; st >>= 1) { if (t < st) red[t] = fmaxf(red[t], red[t + st]); __syncthreads(); }
    float m = red[0]; __syncthreads();
    float e = expf(s - m);
    red[t] = e; __syncthreads();
    for (int st = 128; st > 0; st >>= 1) { if (t < st) red[t] += red[t + st]; __syncthreads(); }
    float S = red[0]; __syncthreads();
    float sm = e / (S + 1e-16f);
    // max(sm) over the graph = sm of the max-score node = expf(0)/(S+eps) = 1/(S+eps), exactly.
    float smax = 1.f / (S + 1e-16f);
    float thr = fminf(smax - 1e-7f, minscore);
    bool keep = sm > thr;
    g_sm[h * NND + i] = sm;
    g_keep[h * NND + i] = keep ? 1 : 0;
    unsigned int bm = __ballot_sync(0xffffffffu, keep);
    if (lane == 0) wb[w] = __popc(bm);
    __syncthreads();
    if (t == 0) {
        int a = 0;
        for (int k = 0; k < 8; k++) { int v = wb[k]; wb[k] = a; a += v; }
        s_nk = a;
    }
    __syncthreads();
    if (keep) slist[wb[w] + __popc(bm & ((1u << lane) - 1u))] = t;
    __syncthreads();
    int nk = s_nk;
    if (t == 0) g_gkcnt[h * 256 + g] = nk;
    for (int li = 0; li < nk; li++) {
        int nl = slist[li];
        if (t < 128) g_new[(size_t)(g * 256 + nl) * 128 + t] = 0.f;
        if (t == 0) { g_klist[h * NND + g * 256 + li] = nl; g_touch[g * 256 + nl] = 1; }
    }
}

// ---------------- head conv on kept nodes + fused stats + finalize (grid (256,4)) -------
__global__ void __launch_bounds__(256) k_headstats(const float* __restrict__ Wrel,
                                                   const float* __restrict__ Wroot,
                                                   const float* __restrict__ bias,
                                                   const float* __restrict__ gamma) {
    __shared__ float s_agg[8][128];
    __shared__ float s_xp[8][128];
    __shared__ float sS[8][32], sQ[8][32];
    int g = blockIdx.x, h = blockIdx.y;
    int kc = g_gkcnt[h * 256 + g];
    int w = threadIdx.x >> 5, lane = threadIdx.x & 31;
    const float* smh = g_sm + h * NND;
    const unsigned char* kph = g_keep + h * NND;
    float s = 0.f, q = 0.f;
    for (int entry = w; entry < kc; entry += 8) {
        int i = g * 256 + g_klist[h * NND + g * 256 + entry];
        int o = g_off[i];
        int c = g_off[i + 1] - o;
        float a0 = -3.402823466e38f, a1 = a0, a2 = a0, a3 = a0;
        bool any = false;
        for (int j = 0; j < c; j++) {
            int sr = g_srcs[o + j];
            if (kph[sr]) {
                any = true;
                float ss = smh[sr];
                const float* cr = g_cur + (size_t)sr * 128;
                a0 = fmaxf(a0, cr[lane]      * ss);
                a1 = fmaxf(a1, cr[lane + 32] * ss);
                a2 = fmaxf(a2, cr[lane + 64] * ss);
                a3 = fmaxf(a3, cr[lane + 96] * ss);
            }
        }
        if (!any) { a0 = a1 = a2 = a3 = 0.f; }
        float smi = smh[i];
        const float* ci = g_cur + (size_t)i * 128;
        s_agg[w][lane] = a0; s_agg[w][lane + 32] = a1; s_agg[w][lane + 64] = a2; s_agg[w][lane + 96] = a3;
        s_xp[w][lane]      = ci[lane]      * smi;
        s_xp[w][lane + 32] = ci[lane + 32] * smi;
        s_xp[w][lane + 64] = ci[lane + 64] * smi;
        s_xp[w][lane + 96] = ci[lane + 96] * smi;
        __syncwarp();
        const float* wr = Wrel  + (h * 32 + lane) * 128;
        const float* wo = Wroot + (h * 32 + lane) * 128;
        float acc = bias[h * 32 + lane];
#pragma unroll 4
        for (int k = 0; k < 128; k++) acc += s_agg[w][k] * wr[k] + s_xp[w][k] * wo[k];
        float v = lrelu(acc);
        g_new[(size_t)i * 128 + h * 32 + lane] = v;
        s += v; q += v * v;
        __syncwarp();
    }
    sS[w][lane] = s; sQ[w][lane] = q;
    __syncthreads();
    if (w == 0) {
        float ss = 0.f, qq = 0.f;
#pragma unroll
        for (int r = 0; r < 8; r++) { ss += sS[r][lane]; qq += sQ[r][lane]; }
        g_partS[(h * 256 + g) * 32 + lane] = ss;
        g_partQ[(h * 256 + g) * 32 + lane] = qq;
    }
    // last-block finalize (1024 blocks)
    __shared__ bool islast;
    __shared__ float rs[256], rq[256];
    __threadfence();
    if (threadIdx.x == 0) {
        unsigned old = atomicInc(&g_done1, 1023);
        islast = (old == 1023);
    }
    __syncthreads();
    if (islast) {
        int t = threadIdx.x;
        int c = t & 127, sl = t >> 7;
        int hh = c >> 5, cc = c & 31;
        float ss = 0.f, qq = 0.f;
#pragma unroll 8
        for (int gg = sl * 128; gg < sl * 128 + 128; gg++) {
            ss += g_partS[(hh * 256 + gg) * 32 + cc];
            qq += g_partQ[(hh * 256 + gg) * 32 + cc];
        }
        rs[t] = ss; rq[t] = qq;
        __syncthreads();
        if (t < 128) {
            float S = rs[t] + rs[t + 128];
            float Q = rq[t] + rq[t + 128];
            float mean = S / (float)NND;
            float var  = Q / (float)NND - mean * mean;
            g_mean[t]  = mean;
            g_gamrs[t] = gamma[t] * rsqrtf(var + 1e-5f);
        }
    }
}

// ---------------- fused classifier: softmax+keep -> gate -> attn pool -> MLP -> logsm ----
__global__ void __launch_bounds__(256) k_cls(const float* __restrict__ gW1, const float* __restrict__ gb1,
                                             const float* __restrict__ gW2, const float* __restrict__ gb2,
                                             const float* __restrict__ fW1, const float* __restrict__ fb1,
                                             const float* __restrict__ fW2, const float* __restrict__ fb2,
                                             float* __restrict__ out) {
    __shared__ float red[256], s_sm[256], s_xp[128], s_term[128], s_gate[256];
    __shared__ int slist[256], wbase[8], s_nk;
    int g = blockIdx.x, c = blockIdx.y, t = threadIdx.x;
    int i = g * 256 + t;
    float s = g_score[c * NND + i];
    red[t] = s; __syncthreads();
    for (int st = 128; st > 0; st >>= 1) { if (t < st) red[t] = fmaxf(red[t], red[t + st]); __syncthreads(); }
    float m = red[0]; __syncthreads();
    float e = expf(s - m);
    red[t] = e; __syncthreads();
    for (int st = 128; st > 0; st >>= 1) { if (t < st) red[t] += red[t + st]; __syncthreads(); }
    float S0 = red[0]; __syncthreads();
    float sm = e / (S0 + 1e-16f);
    float smax = 1.f / (S0 + 1e-16f);     // exact max(sm)
    float thr = fminf(smax - 1e-7f, 0.8f);
    bool keep = sm > thr;
    s_sm[t] = sm;
    int w = t >> 5, lane = t & 31;
    unsigned int bm = __ballot_sync(0xffffffffu, keep);
    if (lane == 0) wbase[w] = __popc(bm);
    __syncthreads();
    if (t == 0) {
        int acc = 0;
        for (int k = 0; k < 8; k++) { int v = wbase[k]; wbase[k] = acc; acc += v; }
        s_nk = acc;
    }
    __syncthreads();
    if (keep) slist[wbase[w] + __popc(bm & ((1u << lane) - 1u))] = t;
    __syncthreads();
    int nk = s_nk;
    int f = t >> 1, hf = t & 1;
    for (int li = 0; li < nk; li++) {
        int tk = slist[li];
        float smk = s_sm[tk];
        if (t < 128) s_xp[t] = g_cur[(size_t)(g * 256 + tk) * 128 + t] * smk;
        __syncthreads();
        const float* w1 = gW1 + ((size_t)c * 128 + f) * 128 + hf * 64;
        float acc = 0.f;
#pragma unroll 8
        for (int k = 0; k < 64; k++) acc += s_xp[hf * 64 + k] * w1[k];
        red[t] = acc; __syncthreads();
        if (t < 128) {
            float comb = red[2 * t] + red[2 * t + 1] + gb1[c * 128 + t];
            s_term[t] = lrelu(comb) * gW2[c * 128 + t];
        }
        __syncthreads();
        for (int st = 64; st > 0; st >>= 1) { if (t < st) s_term[t] += s_term[t + st]; __syncthreads(); }
        if (t == 0) s_gate[li] = s_term[0] + gb2[c];
        __syncthreads();
    }
    if (t == 0) {
        float M = -3.402823466e38f;
        for (int li = 0; li < nk; li++) M = fmaxf(M, s_gate[li]);
        float S = 0.f;
        for (int li = 0; li < nk; li++) S += expf(s_gate[li] - M);
        float inv = 1.f / (S + 1e-16f);
        for (int li = 0; li < nk; li++)
            s_gate[li] = expf(s_gate[li] - M) * inv * s_sm[slist[li]];
    }
    __syncthreads();
    if (t < 128) {
        float pf = 0.f;
        for (int li = 0; li < nk; li++)
            pf += s_gate[li] * g_cur[(size_t)(g * 256 + slist[li]) * 128 + t];
        s_xp[t] = pf;
    }
    __syncthreads();
    const float* w1 = fW1 + ((size_t)c * 128 + f) * 128 + hf * 64;
    float acc = 0.f;
#pragma unroll 8
    for (int k = 0; k < 64; k++) acc += s_xp[hf * 64 + k] * w1[k];
    red[t] = acc; __syncthreads();
    if (t < 128) {
        float comb = red[2 * t] + red[2 * t + 1] + fb1[c * 128 + t];
        s_term[t] = lrelu(comb) * fW2[c * 128 + t];
    }
    __syncthreads();
    for (int st = 64; st > 0; st >>= 1) { if (t < st) s_term[t] += s_term[t + st]; __syncthreads(); }
    // logit + per-graph last-block log_softmax
    if (t == 0) {
        g_logits[g * 4 + c] = s_term[0] + fb2[c];
        __threadfence();
        unsigned old = atomicInc(&g_cdone[g], 3);
        if (old == 3) {
            volatile float* lg = g_logits + g * 4;
            float l0 = lg[0], l1 = lg[1], l2 = lg[2], l3 = lg[3];
            float mm = fmaxf(fmaxf(l0, l1), fmaxf(l2, l3));
            float ss = expf(l0 - mm) + expf(l1 - mm) + expf(l2 - mm) + expf(l3 - mm);
            float ls = mm + logf(ss);
            out[g * 4 + 0] = l0 - ls;
            out[g * 4 + 1] = l1 - ls;
            out[g * 4 + 2] = l2 - ls;
            out[g * 4 + 3] = l3 - ls;
        }
    }
}

// ---------------------------------- launcher ----------------------------------
extern "C" void kernel_launch(void* const* d_in, const int* in_sizes, int n_in,
                              void* d_out, int out_size) {
    const float* x      = (const float*)d_in[0];
    const int*   ei     = (const int*)  d_in[1];
    const int*   src    = ei;
    const int*   dst    = ei + EED;
    const float* Wrel0  = (const float*)d_in[3];
    const float* Wroot0 = (const float*)d_in[4];
    const float* b0     = (const float*)d_in[5];
    const float* bn0g   = (const float*)d_in[6];
    const float* bn0b   = (const float*)d_in[7];
    const float* bpw    = (const float*)d_in[8];
    const float* bWrel  = (const float*)d_in[9];
    const float* bWroot = (const float*)d_in[10];
    const float* bbias  = (const float*)d_in[11];
    const float* bbng   = (const float*)d_in[12];
    const float* bbnb   = (const float*)d_in[13];
    const float* cpw    = (const float*)d_in[14];
    const float* gW1    = (const float*)d_in[15];
    const float* gb1    = (const float*)d_in[16];
    const float* gW2    = (const float*)d_in[17];
    const float* gb2    = (const float*)d_in[18];
    const float* fW1    = (const float*)d_in[19];
    const float* fb1    = (const float*)d_in[20];
    const float* fW2    = (const float*)d_in[21];
    const float* fb2    = (const float*)d_in[22];
    float* out = (float*)d_out;

    // CSR build (g_cnt/g_cnt2 zero on entry, restored by k_agg0)
    k_hist<<<EED / 512, 256>>>(dst);
    k_scan<<<1, 1024>>>();
    k_scatter<<<EED / 512, 256>>>(src, dst);

    // conv0 (+stats finalize inside)
    k_agg0<<<NND / 16, 256>>>(x);
    static int smem_set = 0;
    if (!smem_set) {
        cudaFuncSetAttribute(k_conv0, cudaFuncAttributeMaxDynamicSharedMemorySize,
                             2 * 128 * LDP * 4);
        smem_set = 1;
    }
    k_conv0<<<NND / 128, 256, 2 * 128 * LDP * 4>>>(x, Wrel0, Wroot0, b0, bn0g);
    k_bn_scores<<<NND / 8, 256>>>(bn0b, bpw);

    // 2 multi-head blocks
    for (int bi = 0; bi < 2; bi++) {
        k_softmax<<<dim3(BBD, 4), 256>>>(0.7f);
        k_headstats<<<dim3(BBD, 4), 256>>>(bWrel + bi * 4 * 32 * 128,
                                           bWroot + bi * 4 * 32 * 128,
                                           bbias + bi * 4 * 32,
                                           bbng + bi * 128);
        const float* nextw = (bi == 0) ? (bpw + 4 * 128) : cpw;
        k_res_scores<<<NND / 8, 256>>>(bbnb + bi * 128, nextw);
    }

    // fused classifier + log_softmax (folded)
    k_cls<<<dim3(BBD, 4), 256>>>(gW1, gb1, gW2, gb2, fW1, fb1, fW2, fb2, out);
}

// round 16
// speedup vs baseline: 1.1539x; 1.0903x over previous
#include <cuda_runtime.h>

// Problem constants (fixed by the dataset)
#define NND   65536
#define EED   524288
#define BBD   256
#define EMBD  128
#define FEATD 64

// ---------------- scratch (static __device__ globals; zero-initialized) ----------------
__device__ float g_cur[NND * EMBD];
__device__ float g_new[NND * EMBD];
__device__ float g_agg0[NND * FEATD];
__device__ int   g_off[NND + 1];
__device__ int   g_cnt[NND];      // hist counts   (zeroed by k_agg0 for next call)
__device__ int   g_cnt2[NND];     // scatter cursor(zeroed by k_agg0 for next call)
__device__ int   g_srcs[EED];
__device__ float g_score[4 * NND];
__device__ float g_sm[4 * NND];
__device__ unsigned char g_keep[4 * NND];
__device__ int   g_klist[4 * NND];   // per (head, graph): local node indices, ordered
__device__ int   g_gkcnt[4 * BBD];   // kept count per (head, graph)
__device__ int   g_touch[NND];
__device__ float g_partS[512 * EMBD];
__device__ float g_partQ[512 * EMBD];
__device__ float g_mean[EMBD];
__device__ float g_gamrs[EMBD];
__device__ float g_logits[BBD * 4];
__device__ unsigned int g_done0;        // conv0 finalize counter (wraps to 0)
__device__ unsigned int g_done1;        // headstats finalize counter (wraps to 0)
__device__ unsigned int g_cdone[BBD];   // per-graph k_cls completion (wraps to 0)

__device__ __forceinline__ float lrelu(float v) { return v > 0.f ? v : 0.01f * v; }

// ---------------- CSR build ----------------
__global__ void k_hist(const int* __restrict__ dst) {
    int e = blockIdx.x * 256 + threadIdx.x;
    atomicAdd(&g_cnt[dst[e]], 1);
}

// single-block scan: 1024 threads, 64 contiguous counts each
__global__ void __launch_bounds__(1024) k_scan() {
    __shared__ int wsum[32];
    int t = threadIdx.x, lane = t & 31, w = t >> 5;
    int base = t * 64;
    int s = 0;
#pragma unroll
    for (int i = 0; i < 16; i++) {
        int4 v = *reinterpret_cast<const int4*>(g_cnt + base + i * 4);
        s += v.x + v.y + v.z + v.w;
    }
    int inc = s;
    for (int o = 1; o < 32; o <<= 1) {
        int n = __shfl_up_sync(0xffffffffu, inc, o);
        if (lane >= o) inc += n;
    }
    if (lane == 31) wsum[w] = inc;
    __syncthreads();
    if (w == 0) {
        int v = wsum[lane];
        for (int o = 1; o < 32; o <<= 1) {
            int n = __shfl_up_sync(0xffffffffu, v, o);
            if (lane >= o) v += n;
        }
        wsum[lane] = v;
    }
    __syncthreads();
    int run = ((w > 0) ? wsum[w - 1] : 0) + (inc - s);
#pragma unroll
    for (int i = 0; i < 16; i++) {
        int4 v = *reinterpret_cast<const int4*>(g_cnt + base + i * 4);
        g_off[base + i * 4 + 0] = run; run += v.x;
        g_off[base + i * 4 + 1] = run; run += v.y;
        g_off[base + i * 4 + 2] = run; run += v.z;
        g_off[base + i * 4 + 3] = run; run += v.w;
    }
    if (t == 1023) g_off[NND] = EED;
}

__global__ void k_scatter(const int* __restrict__ src, const int* __restrict__ dst) {
    int e = blockIdx.x * 256 + threadIdx.x;
    int d = dst[e];
    int p = atomicAdd(&g_cnt2[d], 1);
    g_srcs[g_off[d] + p] = src[e];
}

// ---------------- conv0 max aggregation (warp/node, 4-edge unrolled) + cnt reset ----------------
__global__ void k_agg0(const float* __restrict__ x) {
    int gtid = blockIdx.x * blockDim.x + threadIdx.x;
    if (gtid < NND) { g_cnt[gtid] = 0; g_cnt2[gtid] = 0; }   // restore invariant for next call
    int warp = gtid >> 5;
    int lane = threadIdx.x & 31;
    if (warp >= NND) return;
    int o = g_off[warp], e = g_off[warp + 1];
    float2 m = make_float2(-3.402823466e38f, -3.402823466e38f);
    int j = o;
    for (; j + 3 < e; j += 4) {
        int s0 = g_srcs[j], s1 = g_srcs[j + 1], s2 = g_srcs[j + 2], s3 = g_srcs[j + 3];
        float2 v0 = *reinterpret_cast<const float2*>(x + s0 * FEATD + lane * 2);
        float2 v1 = *reinterpret_cast<const float2*>(x + s1 * FEATD + lane * 2);
        float2 v2 = *reinterpret_cast<const float2*>(x + s2 * FEATD + lane * 2);
        float2 v3 = *reinterpret_cast<const float2*>(x + s3 * FEATD + lane * 2);
        m.x = fmaxf(m.x, fmaxf(fmaxf(v0.x, v1.x), fmaxf(v2.x, v3.x)));
        m.y = fmaxf(m.y, fmaxf(fmaxf(v0.y, v1.y), fmaxf(v2.y, v3.y)));
    }
    for (; j < e; j++) {
        int s = g_srcs[j];
        float2 v = *reinterpret_cast<const float2*>(x + s * FEATD + lane * 2);
        m.x = fmaxf(m.x, v.x); m.y = fmaxf(m.y, v.y);
    }
    if (e == o) { m.x = 0.f; m.y = 0.f; }
    *reinterpret_cast<float2*>(g_agg0 + warp * FEATD + lane * 2) = m;
}

// ---------------- conv0 GEMM (scalar 8x8 tile) + fused stats + fast finalize ----------------
#define LDP 132
__global__ void __launch_bounds__(256) k_conv0(const float* __restrict__ x,
                                               const float* __restrict__ Wrel,
                                               const float* __restrict__ Wroot,
                                               const float* __restrict__ bias,
                                               const float* __restrict__ gamma) {
    extern __shared__ float sh[];
    float* sA = sh;              // [128 k][LDP] nodes contiguous
    float* sW = sh + 128 * LDP;  // [128 k][LDP] feats contiguous
    int t = threadIdx.x;
    int nbase = blockIdx.x * 128;
    for (int idx = t; idx < 8192; idx += 256) {
        int f = idx >> 6, k = idx & 63;
        sW[k * LDP + f]        = Wrel[idx];
        sW[(k + 64) * LDP + f] = Wroot[idx];
    }
    for (int idx = t; idx < 8192; idx += 256) {
        int node = idx >> 6, k = idx & 63;
        sA[k * LDP + node]        = g_agg0[nbase * 64 + idx];
        sA[(k + 64) * LDP + node] = x[nbase * 64 + idx];
    }
    __syncthreads();
    int tx = t & 15, ty = t >> 4;
    int f0 = tx * 8, n0 = ty * 8;
    float acc[8][8];
#pragma unroll
    for (int i = 0; i < 8; i++)
#pragma unroll
        for (int j = 0; j < 8; j++) acc[i][j] = 0.f;
#pragma unroll 2
    for (int k = 0; k < 128; k++) {
        float4 a0 = *reinterpret_cast<float4*>(sA + k * LDP + n0);
        float4 a1 = *reinterpret_cast<float4*>(sA + k * LDP + n0 + 4);
        float4 w0 = *reinterpret_cast<float4*>(sW + k * LDP + f0);
        float4 w1 = *reinterpret_cast<float4*>(sW + k * LDP + f0 + 4);
        float av[8] = {a0.x, a0.y, a0.z, a0.w, a1.x, a1.y, a1.z, a1.w};
        float wv[8] = {w0.x, w0.y, w0.z, w0.w, w1.x, w1.y, w1.z, w1.w};
#pragma unroll
        for (int i = 0; i < 8; i++)
#pragma unroll
            for (int j = 0; j < 8; j++) acc[i][j] += av[i] * wv[j];
    }
    float bb[8], s[8], q[8];
#pragma unroll
    for (int j = 0; j < 8; j++) { bb[j] = bias[f0 + j]; s[j] = 0.f; q[j] = 0.f; }
#pragma unroll
    for (int i = 0; i < 8; i++) {
        float v[8];
#pragma unroll
        for (int j = 0; j < 8; j++) {
            v[j] = lrelu(acc[i][j] + bb[j]);
            s[j] += v[j]; q[j] += v[j] * v[j];
        }
        float4* outp = reinterpret_cast<float4*>(g_new + (size_t)(nbase + n0 + i) * 128 + f0);
        outp[0] = make_float4(v[0], v[1], v[2], v[3]);
        outp[1] = make_float4(v[4], v[5], v[6], v[7]);
    }
    __syncthreads();
    float* sS = sA;
    float* sQ = sA + 2048;
#pragma unroll
    for (int j = 0; j < 8; j++) { sS[ty * 128 + f0 + j] = s[j]; sQ[ty * 128 + f0 + j] = q[j]; }
    __syncthreads();
    if (t < 128) {
        float ss = 0.f, qq = 0.f;
        for (int r = 0; r < 16; r++) { ss += sS[r * 128 + t]; qq += sQ[r * 128 + t]; }
        g_partS[blockIdx.x * 128 + t] = ss;
        g_partQ[blockIdx.x * 128 + t] = qq;
    }
    // last-block finalize: S on threads 0-127, Q on threads 128-255, deep unroll
    __shared__ bool islast;
    __shared__ float rr[256];
    __threadfence();
    if (t == 0) {
        unsigned old = atomicInc(&g_done0, gridDim.x - 1);
        islast = (old == gridDim.x - 1);
    }
    __syncthreads();
    if (islast) {
        int col = t & 127;
        float a = 0.f;
        if (t < 128) {
#pragma unroll 16
            for (int ch = 0; ch < 512; ch++) a += g_partS[ch * 128 + col];
        } else {
#pragma unroll 16
            for (int ch = 0; ch < 512; ch++) a += g_partQ[ch * 128 + col];
        }
        rr[t] = a;
        __syncthreads();
        if (t < 128) {
            float S = rr[t], Q = rr[t + 128];
            float mean = S / (float)NND;
            float var  = Q / (float)NND - mean * mean;
            g_mean[t]  = mean;
            g_gamrs[t] = gamma[t] * rsqrtf(var + 1e-5f);
        }
    }
}

// ---------------- fused BN-apply + pooling scores (4 nodes/warp, grid 2048) ----------------
__global__ void __launch_bounds__(256) k_bn_scores(const float* __restrict__ beta,
                                                   const float* __restrict__ w4) {
    __shared__ float sw[512], s_m[128], s_g[128], s_b[128];
    int t = threadIdx.x;
    for (int i = t; i < 512; i += 256) sw[i] = w4[i];
    if (t < 128) { s_m[t] = g_mean[t]; s_g[t] = g_gamrs[t]; s_b[t] = beta[t]; }
    __syncthreads();
    int w = t >> 5, lane = t & 31;
    int f = lane * 4;
    float m0 = s_m[f],     m1 = s_m[f + 1], m2 = s_m[f + 2], m3 = s_m[f + 3];
    float g0 = s_g[f],     g1 = s_g[f + 1], g2 = s_g[f + 2], g3 = s_g[f + 3];
    float b0 = s_b[f],     b1 = s_b[f + 1], b2 = s_b[f + 2], b3 = s_b[f + 3];
#pragma unroll
    for (int n = 0; n < 4; n++) {
        int node = blockIdx.x * 32 + w * 4 + n;
        float4 v = *reinterpret_cast<const float4*>(g_new + (size_t)node * 128 + f);
        float4 c;
        c.x = (v.x - m0) * g0 + b0;
        c.y = (v.y - m1) * g1 + b1;
        c.z = (v.z - m2) * g2 + b2;
        c.w = (v.w - m3) * g3 + b3;
        *reinterpret_cast<float4*>(g_cur + (size_t)node * 128 + f) = c;
#pragma unroll
        for (int h = 0; h < 4; h++) {
            const float* ww = sw + h * 128 + f;
            float p = c.x * ww[0] + c.y * ww[1] + c.z * ww[2] + c.w * ww[3];
            for (int o = 16; o > 0; o >>= 1) p += __shfl_xor_sync(0xffffffffu, p, o);
            if (lane == 0) g_score[h * NND + node] = p;
        }
    }
}

// ---------------- fused residual + pooling scores (4 nodes/warp; +touch clear) ----------------
__global__ void __launch_bounds__(256) k_res_scores(const float* __restrict__ beta,
                                                    const float* __restrict__ w4) {
    __shared__ float sw[512], s_m[128], s_g[128], s_b[128];
    int t = threadIdx.x;
    for (int i = t; i < 512; i += 256) sw[i] = w4[i];
    if (t < 128) { s_m[t] = g_mean[t]; s_g[t] = g_gamrs[t]; s_b[t] = beta[t]; }
    __syncthreads();
    int w = t >> 5, lane = t & 31;
    int f = lane * 4;
    float m0 = s_m[f],     m1 = s_m[f + 1], m2 = s_m[f + 2], m3 = s_m[f + 3];
    float g0 = s_g[f],     g1 = s_g[f + 1], g2 = s_g[f + 2], g3 = s_g[f + 3];
    float b0 = s_b[f],     b1 = s_b[f + 1], b2 = s_b[f + 2], b3 = s_b[f + 3];
#pragma unroll
    for (int n = 0; n < 4; n++) {
        int node = blockIdx.x * 32 + w * 4 + n;
        int tch = g_touch[node];
        float4 v = make_float4(0.f, 0.f, 0.f, 0.f);
        if (tch) v = *reinterpret_cast<const float4*>(g_new + (size_t)node * 128 + f);
        float4 cu = *reinterpret_cast<const float4*>(g_cur + (size_t)node * 128 + f);
        float4 c;
        c.x = 0.5f * cu.x + 0.25f * ((v.x - m0) * g0 + b0);
        c.y = 0.5f * cu.y + 0.25f * ((v.y - m1) * g1 + b1);
        c.z = 0.5f * cu.z + 0.25f * ((v.z - m2) * g2 + b2);
        c.w = 0.5f * cu.w + 0.25f * ((v.w - m3) * g3 + b3);
        *reinterpret_cast<float4*>(g_cur + (size_t)node * 128 + f) = c;
#pragma unroll
        for (int h = 0; h < 4; h++) {
            const float* ww = sw + h * 128 + f;
            float p = c.x * ww[0] + c.y * ww[1] + c.z * ww[2] + c.w * ww[3];
            for (int o = 16; o > 0; o >>= 1) p += __shfl_xor_sync(0xffffffffu, p, o);
            if (lane == 0) g_score[h * NND + node] = p;
        }
    }
    __syncthreads();
    if (t < 32) g_touch[blockIdx.x * 32 + t] = 0;
}

// ---------------- per-graph softmax + keep + ORDERED compaction + kept-row zero/touch ----
__global__ void k_softmax(float minscore) {  // grid (B, 4) x 256
    __shared__ float red[256];
    __shared__ int slist[256], wb[8];
    __shared__ int s_nk;
    int g = blockIdx.x, h = blockIdx.y, t = threadIdx.x;
    int w = t >> 5, lane = t & 31;
    int i = g * 256 + t;
    float s = g_score[h * NND + i];
    red[t] = s; __syncthreads();
    for (int st = 128; st > 0; st >>= 1) { if (t < st) red[t] = fmaxf(red[t], red[t + st]); __syncthreads(); }
    float m = red[0]; __syncthreads();
    float e = expf(s - m);
    red[t] = e; __syncthreads();
    for (int st = 128; st > 0; st >>= 1) { if (t < st) red[t] += red[t + st]; __syncthreads(); }
    float S = red[0]; __syncthreads();
    float sm = e / (S + 1e-16f);
    float smax = 1.f / (S + 1e-16f);   // exact max(sm)
    float thr = fminf(smax - 1e-7f, minscore);
    bool keep = sm > thr;
    g_sm[h * NND + i] = sm;
    g_keep[h * NND + i] = keep ? 1 : 0;
    unsigned int bm = __ballot_sync(0xffffffffu, keep);
    if (lane == 0) wb[w] = __popc(bm);
    __syncthreads();
    if (t == 0) {
        int a = 0;
        for (int k = 0; k < 8; k++) { int v = wb[k]; wb[k] = a; a += v; }
        s_nk = a;
    }
    __syncthreads();
    if (keep) slist[wb[w] + __popc(bm & ((1u << lane) - 1u))] = t;
    __syncthreads();
    int nk = s_nk;
    if (t == 0) g_gkcnt[h * 256 + g] = nk;
    for (int li = 0; li < nk; li++) {
        int nl = slist[li];
        if (t < 128) g_new[(size_t)(g * 256 + nl) * 128 + t] = 0.f;
        if (t == 0) { g_klist[h * NND + g * 256 + li] = nl; g_touch[g * 256 + nl] = 1; }
    }
}

// ---------------- head conv on kept nodes + fused stats + fast finalize (grid (256,4)) ---
__global__ void __launch_bounds__(256) k_headstats(const float* __restrict__ Wrel,
                                                   const float* __restrict__ Wroot,
                                                   const float* __restrict__ bias,
                                                   const float* __restrict__ gamma) {
    __shared__ float s_agg[8][128];
    __shared__ float s_xp[8][128];
    __shared__ float sS[8][32], sQ[8][32];
    int g = blockIdx.x, h = blockIdx.y;
    int kc = g_gkcnt[h * 256 + g];
    int w = threadIdx.x >> 5, lane = threadIdx.x & 31;
    const float* smh = g_sm + h * NND;
    const unsigned char* kph = g_keep + h * NND;
    float s = 0.f, q = 0.f;
    for (int entry = w; entry < kc; entry += 8) {
        int i = g * 256 + g_klist[h * NND + g * 256 + entry];
        int o = g_off[i];
        int c = g_off[i + 1] - o;
        float a0 = -3.402823466e38f, a1 = a0, a2 = a0, a3 = a0;
        bool any = false;
        for (int j = 0; j < c; j++) {
            int sr = g_srcs[o + j];
            if (kph[sr]) {
                any = true;
                float ss = smh[sr];
                const float* cr = g_cur + (size_t)sr * 128;
                a0 = fmaxf(a0, cr[lane]      * ss);
                a1 = fmaxf(a1, cr[lane + 32] * ss);
                a2 = fmaxf(a2, cr[lane + 64] * ss);
                a3 = fmaxf(a3, cr[lane + 96] * ss);
            }
        }
        if (!any) { a0 = a1 = a2 = a3 = 0.f; }
        float smi = smh[i];
        const float* ci = g_cur + (size_t)i * 128;
        s_agg[w][lane] = a0; s_agg[w][lane + 32] = a1; s_agg[w][lane + 64] = a2; s_agg[w][lane + 96] = a3;
        s_xp[w][lane]      = ci[lane]      * smi;
        s_xp[w][lane + 32] = ci[lane + 32] * smi;
        s_xp[w][lane + 64] = ci[lane + 64] * smi;
        s_xp[w][lane + 96] = ci[lane + 96] * smi;
        __syncwarp();
        const float* wr = Wrel  + (h * 32 + lane) * 128;
        const float* wo = Wroot + (h * 32 + lane) * 128;
        float acc = bias[h * 32 + lane];
#pragma unroll 4
        for (int k = 0; k < 128; k++) acc += s_agg[w][k] * wr[k] + s_xp[w][k] * wo[k];
        float v = lrelu(acc);
        g_new[(size_t)i * 128 + h * 32 + lane] = v;
        s += v; q += v * v;
        __syncwarp();
    }
    sS[w][lane] = s; sQ[w][lane] = q;
    __syncthreads();
    if (w == 0) {
        float ss = 0.f, qq = 0.f;
#pragma unroll
        for (int r = 0; r < 8; r++) { ss += sS[r][lane]; qq += sQ[r][lane]; }
        g_partS[(h * 256 + g) * 32 + lane] = ss;
        g_partQ[(h * 256 + g) * 32 + lane] = qq;
    }
    // last-block finalize: S on threads 0-127, Q on 128-255
    __shared__ bool islast;
    __shared__ float rr[256];
    __threadfence();
    if (threadIdx.x == 0) {
        unsigned old = atomicInc(&g_done1, 1023);
        islast = (old == 1023);
    }
    __syncthreads();
    if (islast) {
        int t = threadIdx.x;
        int c = t & 127;
        int hh = c >> 5, cc = c & 31;
        float a = 0.f;
        if (t < 128) {
#pragma unroll 16
            for (int gg = 0; gg < 256; gg++) a += g_partS[(hh * 256 + gg) * 32 + cc];
        } else {
#pragma unroll 16
            for (int gg = 0; gg < 256; gg++) a += g_partQ[(hh * 256 + gg) * 32 + cc];
        }
        rr[t] = a;
        __syncthreads();
        if (t < 128) {
            float S = rr[t], Q = rr[t + 128];
            float mean = S / (float)NND;
            float var  = Q / (float)NND - mean * mean;
            g_mean[t]  = mean;
            g_gamrs[t] = gamma[t] * rsqrtf(var + 1e-5f);
        }
    }
}

// ---------------- fused classifier: softmax+keep -> gate -> attn pool -> MLP -> logsm ----
__global__ void __launch_bounds__(256) k_cls(const float* __restrict__ gW1, const float* __restrict__ gb1,
                                             const float* __restrict__ gW2, const float* __restrict__ gb2,
                                             const float* __restrict__ fW1, const float* __restrict__ fb1,
                                             const float* __restrict__ fW2, const float* __restrict__ fb2,
                                             float* __restrict__ out) {
    __shared__ float red[256], s_sm[256], s_xp[128], s_term[128], s_gate[256];
    __shared__ int slist[256], wbase[8], s_nk;
    int g = blockIdx.x, c = blockIdx.y, t = threadIdx.x;
    int i = g * 256 + t;
    float s = g_score[c * NND + i];
    red[t] = s; __syncthreads();
    for (int st = 128; st > 0; st >>= 1) { if (t < st) red[t] = fmaxf(red[t], red[t + st]); __syncthreads(); }
    float m = red[0]; __syncthreads();
    float e = expf(s - m);
    red[t] = e; __syncthreads();
    for (int st = 128; st > 0; st >>= 1) { if (t < st) red[t] += red[t + st]; __syncthreads(); }
    float S0 = red[0]; __syncthreads();
    float sm = e / (S0 + 1e-16f);
    float smax = 1.f / (S0 + 1e-16f);   // exact max(sm)
    float thr = fminf(smax - 1e-7f, 0.8f);
    bool keep = sm > thr;
    s_sm[t] = sm;
    int w = t >> 5, lane = t & 31;
    unsigned int bm = __ballot_sync(0xffffffffu, keep);
    if (lane == 0) wbase[w] = __popc(bm);
    __syncthreads();
    if (t == 0) {
        int acc = 0;
        for (int k = 0; k < 8; k++) { int v = wbase[k]; wbase[k] = acc; acc += v; }
        s_nk = acc;
    }
    __syncthreads();
    if (keep) slist[wbase[w] + __popc(bm & ((1u << lane) - 1u))] = t;
    __syncthreads();
    int nk = s_nk;
    int f = t >> 1, hf = t & 1;
    for (int li = 0; li < nk; li++) {
        int tk = slist[li];
        float smk = s_sm[tk];
        if (t < 128) s_xp[t] = g_cur[(size_t)(g * 256 + tk) * 128 + t] * smk;
        __syncthreads();
        const float* w1 = gW1 + ((size_t)c * 128 + f) * 128 + hf * 64;
        float acc = 0.f;
#pragma unroll 8
        for (int k = 0; k < 64; k++) acc += s_xp[hf * 64 + k] * w1[k];
        red[t] = acc; __syncthreads();
        if (t < 128) {
            float comb = red[2 * t] + red[2 * t + 1] + gb1[c * 128 + t];
            s_term[t] = lrelu(comb) * gW2[c * 128 + t];
        }
        __syncthreads();
        for (int st = 64; st > 0; st >>= 1) { if (t < st) s_term[t] += s_term[t + st]; __syncthreads(); }
        if (t == 0) s_gate[li] = s_term[0] + gb2[c];
        __syncthreads();
    }
    if (t == 0) {
        float M = -3.402823466e38f;
        for (int li = 0; li < nk; li++) M = fmaxf(M, s_gate[li]);
        float S = 0.f;
        for (int li = 0; li < nk; li++) S += expf(s_gate[li] - M);
        float inv = 1.f / (S + 1e-16f);
        for (int li = 0; li < nk; li++)
            s_gate[li] = expf(s_gate[li] - M) * inv * s_sm[slist[li]];
    }
    __syncthreads();
    if (t < 128) {
        float pf = 0.f;
        for (int li = 0; li < nk; li++)
            pf += s_gate[li] * g_cur[(size_t)(g * 256 + slist[li]) * 128 + t];
        s_xp[t] = pf;
    }
    __syncthreads();
    const float* w1 = fW1 + ((size_t)c * 128 + f) * 128 + hf * 64;
    float acc = 0.f;
#pragma unroll 8
    for (int k = 0; k < 64; k++) acc += s_xp[hf * 64 + k] * w1[k];
    red[t] = acc; __syncthreads();
    if (t < 128) {
        float comb = red[2 * t] + red[2 * t + 1] + fb1[c * 128 + t];
        s_term[t] = lrelu(comb) * fW2[c * 128 + t];
    }
    __syncthreads();
    for (int st = 64; st > 0; st >>= 1) { if (t < st) s_term[t] += s_term[t + st]; __syncthreads(); }
    // logit + per-graph last-block log_softmax
    if (t == 0) {
        g_logits[g * 4 + c] = s_term[0] + fb2[c];
        __threadfence();
        unsigned old = atomicInc(&g_cdone[g], 3);
        if (old == 3) {
            volatile float* lg = g_logits + g * 4;
            float l0 = lg[0], l1 = lg[1], l2 = lg[2], l3 = lg[3];
            float mm = fmaxf(fmaxf(l0, l1), fmaxf(l2, l3));
            float ss = expf(l0 - mm) + expf(l1 - mm) + expf(l2 - mm) + expf(l3 - mm);
            float ls = mm + logf(ss);
            out[g * 4 + 0] = l0 - ls;
            out[g * 4 + 1] = l1 - ls;
            out[g * 4 + 2] = l2 - ls;
            out[g * 4 + 3] = l3 - ls;
        }
    }
}

// ---------------------------------- launcher ----------------------------------
extern "C" void kernel_launch(void* const* d_in, const int* in_sizes, int n_in,
                              void* d_out, int out_size) {
    const float* x      = (const float*)d_in[0];
    const int*   ei     = (const int*)  d_in[1];
    const int*   src    = ei;
    const int*   dst    = ei + EED;
    const float* Wrel0  = (const float*)d_in[3];
    const float* Wroot0 = (const float*)d_in[4];
    const float* b0     = (const float*)d_in[5];
    const float* bn0g   = (const float*)d_in[6];
    const float* bn0b   = (const float*)d_in[7];
    const float* bpw    = (const float*)d_in[8];
    const float* bWrel  = (const float*)d_in[9];
    const float* bWroot = (const float*)d_in[10];
    const float* bbias  = (const float*)d_in[11];
    const float* bbng   = (const float*)d_in[12];
    const float* bbnb   = (const float*)d_in[13];
    const float* cpw    = (const float*)d_in[14];
    const float* gW1    = (const float*)d_in[15];
    const float* gb1    = (const float*)d_in[16];
    const float* gW2    = (const float*)d_in[17];
    const float* gb2    = (const float*)d_in[18];
    const float* fW1    = (const float*)d_in[19];
    const float* fb1    = (const float*)d_in[20];
    const float* fW2    = (const float*)d_in[21];
    const float* fb2    = (const float*)d_in[22];
    float* out = (float*)d_out;

    // CSR build (g_cnt/g_cnt2 zero on entry, restored by k_agg0)
    k_hist<<<EED / 256, 256>>>(dst);
    k_scan<<<1, 1024>>>();
    k_scatter<<<EED / 256, 256>>>(src, dst);

    // conv0 (+stats finalize inside)
    k_agg0<<<NND / 8, 256>>>(x);
    static int smem_set = 0;
    if (!smem_set) {
        cudaFuncSetAttribute(k_conv0, cudaFuncAttributeMaxDynamicSharedMemorySize,
                             2 * 128 * LDP * 4);
        smem_set = 1;
    }
    k_conv0<<<NND / 128, 256, 2 * 128 * LDP * 4>>>(x, Wrel0, Wroot0, b0, bn0g);
    k_bn_scores<<<NND / 32, 256>>>(bn0b, bpw);

    // 2 multi-head blocks
    for (int bi = 0; bi < 2; bi++) {
        k_softmax<<<dim3(BBD, 4), 256>>>(0.7f);
        k_headstats<<<dim3(BBD, 4), 256>>>(bWrel + bi * 4 * 32 * 128,
                                           bWroot + bi * 4 * 32 * 128,
                                           bbias + bi * 4 * 32,
                                           bbng + bi * 128);
        const float* nextw = (bi == 0) ? (bpw + 4 * 128) : cpw;
        k_res_scores<<<NND / 32, 256>>>(bbnb + bi * 128, nextw);
    }

    // fused classifier + log_softmax (folded)
    k_cls<<<dim3(BBD, 4), 256>>>(gW1, gb1, gW2, gb2, fW1, fb1, fW2, fb2, out);
}